// round 12
// baseline (speedup 1.0000x reference)
#include <cuda_runtime.h>
#include <cuda_bf16.h>
#include <math.h>
#include <stdint.h>

// Problem constants
#define BATCH   2
#define SEQ     2048
#define DMODEL  1024
#define HEADS   16
#define DHEAD   64
#define INNER   (HEADS * DHEAD)          // 1024
#define BS      (BATCH * SEQ)            // 4096
#define QKV_N   (3 * INNER)              // 3072
#define KSPLIT  (3 * DMODEL)             // 3072 (hi | lo | hi split along K)
#define BH      (BATCH * HEADS)          // 32

// -------------------- scratch (static device allocations) --------------------
__device__ __nv_bfloat16 g_abuf[BS * KSPLIT];             // split A (x, then ctx)
__device__ __nv_bfloat16 g_bt_qkv[QKV_N * KSPLIT];        // split w_qkv^T
__device__ __nv_bfloat16 g_bt_out[DMODEL * KSPLIT];       // split w_out^T
// attention operands, bf16 hi/lo, all [bh, s, d]
__device__ __nv_bfloat16 g_qh[BH * SEQ * DHEAD];          // scaled+roped q hi
__device__ __nv_bfloat16 g_ql[BH * SEQ * DHEAD];
__device__ __nv_bfloat16 g_kh[BH * SEQ * DHEAD];          // roped k hi
__device__ __nv_bfloat16 g_kl[BH * SEQ * DHEAD];
__device__ __nv_bfloat16 g_vh[BH * SEQ * DHEAD];
__device__ __nv_bfloat16 g_vl[BH * SEQ * DHEAD];
__device__ float2 g_cs[SEQ * 32];                         // (cos, sin) table

// ==================== PTX helpers (sm_80-era, safe at compute_100) ===========
__device__ __forceinline__ uint32_t smem_u32(const void* p) {
    return (uint32_t)__cvta_generic_to_shared(p);
}
__device__ __forceinline__ void cp_async16(uint32_t dst, const void* src) {
    asm volatile("cp.async.cg.shared.global [%0], [%1], 16;\n" :: "r"(dst), "l"(src));
}
__device__ __forceinline__ void cp_commit() {
    asm volatile("cp.async.commit_group;\n" ::: "memory");
}
__device__ __forceinline__ void ldmatrix_x4(uint32_t* r, uint32_t addr) {
    asm volatile("ldmatrix.sync.aligned.m8n8.x4.shared.b16 {%0,%1,%2,%3}, [%4];"
                 : "=r"(r[0]), "=r"(r[1]), "=r"(r[2]), "=r"(r[3]) : "r"(addr));
}
__device__ __forceinline__ void ldmatrix_x4_trans(uint32_t* r, uint32_t addr) {
    asm volatile("ldmatrix.sync.aligned.m8n8.x4.trans.shared.b16 {%0,%1,%2,%3}, [%4];"
                 : "=r"(r[0]), "=r"(r[1]), "=r"(r[2]), "=r"(r[3]) : "r"(addr));
}
__device__ __forceinline__ void mma16816(float* c, const uint32_t* a,
                                         uint32_t b0, uint32_t b1) {
    asm volatile(
        "mma.sync.aligned.m16n8k16.row.col.f32.bf16.bf16.f32 "
        "{%0,%1,%2,%3}, {%4,%5,%6,%7}, {%8,%9}, {%0,%1,%2,%3};"
        : "+f"(c[0]), "+f"(c[1]), "+f"(c[2]), "+f"(c[3])
        : "r"(a[0]), "r"(a[1]), "r"(a[2]), "r"(a[3]), "r"(b0), "r"(b1));
}
__device__ __forceinline__ uint32_t sw128(uint32_t off) {
    return off ^ ((off >> 3) & 0x70);
}
// hi/lo split a pair of fp32 into two bf16x2
__device__ __forceinline__ void split2(float v0, float v1,
                                       __nv_bfloat162& hp, __nv_bfloat162& lp) {
    hp.x = __float2bfloat16(v0);
    hp.y = __float2bfloat16(v1);
    lp.x = __float2bfloat16(v0 - __bfloat162float(hp.x));
    lp.y = __float2bfloat16(v1 - __bfloat162float(hp.y));
}

// ==================== cos/sin table ====================
__global__ __launch_bounds__(256) void init_cs() {
    int t = blockIdx.x * 256 + threadIdx.x;    // 0 .. SEQ*32-1
    int s = t >> 5, i = t & 31;
    float inv_freq = powf(10000.f, -(float)i / 32.f);
    float ang = (float)s * inv_freq;
    float sn, cn;
    __sincosf(ang, &sn, &cn);
    g_cs[t] = make_float2(cn, sn);
}

// ==================== conversion kernels (hi/lo bf16 split) ====================
// in [M,1024] fp32 row-major -> out [M,3072] bf16:  [hi | lo | hi]
__global__ __launch_bounds__(256) void split_rows(const float* __restrict__ in,
                                                  __nv_bfloat16* __restrict__ out) {
    int idx = blockIdx.x * 256 + threadIdx.x;
    int m  = idx >> 8;
    int kq = idx & 255;
    float4 v = ((const float4*)in)[(size_t)m * 256 + kq];
    __nv_bfloat162 hA, hB, lA, lB;
    split2(v.x, v.y, hA, lA);
    split2(v.z, v.w, hB, lB);
    __nv_bfloat162* o = (__nv_bfloat162*)(out + (size_t)m * KSPLIT + kq * 4);
    o[0] = hA; o[1] = hB;
    o[512] = lA; o[513] = lB;
    o[1024] = hA; o[1025] = hB;
}

// W [K,N] fp32 -> BT [N,3K] bf16 with [hi | hi | lo] along k'
__global__ __launch_bounds__(256) void split_bt(const float* __restrict__ W,
                                                __nv_bfloat16* __restrict__ BT,
                                                int K, int N) {
    __shared__ float tile[32][33];
    int k0 = blockIdx.x * 32, n0 = blockIdx.y * 32;
    for (int i = threadIdx.x; i < 1024; i += 256) {
        int r = i >> 5, c = i & 31;
        tile[r][c] = W[(size_t)(k0 + r) * N + n0 + c];
    }
    __syncthreads();
    for (int i = threadIdx.x; i < 1024; i += 256) {
        int rn = i >> 5, kc = i & 31;
        float v = tile[kc][rn];
        __nv_bfloat16 hi = __float2bfloat16(v);
        __nv_bfloat16 lo = __float2bfloat16(v - __bfloat162float(hi));
        __nv_bfloat16* row = BT + (size_t)(n0 + rn) * (3 * K) + k0 + kc;
        row[0]     = hi;
        row[K]     = hi;
        row[2 * K] = lo;
    }
}

// ==================== shared GEMM mainloop ============
// CTA tile 128x128, BK=64, 128 threads = 2x2 warps of 64x64.
// 3-stage cp.async pipeline, SINGLE __syncthreads per chunk:
//   iter c: wait(chunk c) ; sync ; issue load c+2 into stage (c+2)%3
//           (that stage was last read at iter c-1, proven done by this sync) ; compute c.

// ---- generic GEMM (used for out-projection): C fp32 [M,N] ----
__global__ __launch_bounds__(128) void bf16gemm_mma(const __nv_bfloat16* __restrict__ A,
                                                    const __nv_bfloat16* __restrict__ BT,
                                                    float* __restrict__ C,
                                                    int M, int N, int Kp) {
    extern __shared__ __align__(1024) char smem[];
    const uint32_t base = smem_u32(smem);
    const int tid  = threadIdx.x;
    const int wid  = tid >> 5;
    const int lane = tid & 31;
    const int wr   = wid >> 1;
    const int wc   = wid & 1;

    const int brow = blockIdx.y * 128;
    const int bcol = blockIdx.x * 128;
    const int nc   = Kp / 64;

    const __nv_bfloat16* Abase = A + (size_t)brow * Kp;
    const __nv_bfloat16* Bbase = BT + (size_t)bcol * Kp;

    auto load_stage = [&](int chunk, int s) {
        uint32_t sa = base + s * 32768;
        uint32_t sb = sa + 16384;
        const __nv_bfloat16* ac = Abase + chunk * 64;
        const __nv_bfloat16* bc = Bbase + chunk * 64;
        #pragma unroll
        for (int i = 0; i < 8; i++) {
            int l = tid + i * 128;
            int r = l >> 3;
            int c = l & 7;
            uint32_t sw = sw128((uint32_t)(r * 128 + c * 16));
            cp_async16(sa + sw, ac + (size_t)r * Kp + c * 8);
            cp_async16(sb + sw, bc + (size_t)r * Kp + c * 8);
        }
        cp_commit();
    };

    float acc[4][8][4];
    #pragma unroll
    for (int mi = 0; mi < 4; mi++)
        #pragma unroll
        for (int ni = 0; ni < 8; ni++)
            #pragma unroll
            for (int j = 0; j < 4; j++) acc[mi][ni][j] = 0.f;

    load_stage(0, 0);
    load_stage(1, 1);

    const int a_row_off = wr * 64 + (lane & 15);
    const int a_chunk_h = lane >> 4;
    const int b_row_off = wc * 64 + ((lane >> 4) << 3) + (lane & 7);
    const int b_chunk_h = (lane >> 3) & 1;

    for (int c = 0; c < nc; c++) {
        int s = c % 3;
        if (c + 1 < nc) asm volatile("cp.async.wait_group 1;" ::: "memory");
        else            asm volatile("cp.async.wait_group 0;" ::: "memory");
        __syncthreads();
        if (c + 2 < nc) load_stage(c + 2, (c + 2) % 3);

        uint32_t sa = base + s * 32768;
        uint32_t sb = sa + 16384;

        #pragma unroll
        for (int ks = 0; ks < 4; ks++) {
            uint32_t a[4][4];
            #pragma unroll
            for (int mi = 0; mi < 4; mi++) {
                uint32_t off = (uint32_t)((a_row_off + mi * 16) * 128
                                          + (ks * 2 + a_chunk_h) * 16);
                ldmatrix_x4(a[mi], sa + sw128(off));
            }
            uint32_t b[4][4];
            #pragma unroll
            for (int g = 0; g < 4; g++) {
                uint32_t off = (uint32_t)((b_row_off + g * 16) * 128
                                          + (ks * 2 + b_chunk_h) * 16);
                ldmatrix_x4(b[g], sb + sw128(off));
            }
            #pragma unroll
            for (int mi = 0; mi < 4; mi++)
                #pragma unroll
                for (int g = 0; g < 4; g++) {
                    mma16816(acc[mi][2 * g],     a[mi], b[g][0], b[g][1]);
                    mma16816(acc[mi][2 * g + 1], a[mi], b[g][2], b[g][3]);
                }
        }
    }

    #pragma unroll
    for (int mi = 0; mi < 4; mi++) {
        int row0 = brow + wr * 64 + mi * 16 + (lane >> 2);
        #pragma unroll
        for (int ni = 0; ni < 8; ni++) {
            int col = bcol + wc * 64 + ni * 8 + (lane & 3) * 2;
            float2 v0 = {acc[mi][ni][0], acc[mi][ni][1]};
            float2 v1 = {acc[mi][ni][2], acc[mi][ni][3]};
            *(float2*)(C + (size_t)row0 * N + col) = v0;
            *(float2*)(C + (size_t)(row0 + 8) * N + col) = v1;
        }
    }
}

// ---- QKV GEMM with fused RoPE + hi/lo split epilogue ----
__global__ __launch_bounds__(128) void qkvgemm_rope(const __nv_bfloat16* __restrict__ A,
                                                    const __nv_bfloat16* __restrict__ BT) {
    extern __shared__ __align__(1024) char smem[];
    const uint32_t base = smem_u32(smem);
    const int tid  = threadIdx.x;
    const int wid  = tid >> 5;
    const int lane = tid & 31;
    const int wr   = wid >> 1;
    const int wc   = wid & 1;

    const int brow = blockIdx.y * 128;
    const int bcol = blockIdx.x * 128;
    const int Kp   = KSPLIT;
    const int nc   = Kp / 64;

    const __nv_bfloat16* Abase = A + (size_t)brow * Kp;
    const __nv_bfloat16* Bbase = BT + (size_t)bcol * Kp;

    auto load_stage = [&](int chunk, int s) {
        uint32_t sa = base + s * 32768;
        uint32_t sb = sa + 16384;
        const __nv_bfloat16* ac = Abase + chunk * 64;
        const __nv_bfloat16* bc = Bbase + chunk * 64;
        #pragma unroll
        for (int i = 0; i < 8; i++) {
            int l = tid + i * 128;
            int r = l >> 3;
            int c = l & 7;
            uint32_t sw = sw128((uint32_t)(r * 128 + c * 16));
            cp_async16(sa + sw, ac + (size_t)r * Kp + c * 8);
            cp_async16(sb + sw, bc + (size_t)r * Kp + c * 8);
        }
        cp_commit();
    };

    float acc[4][8][4];
    #pragma unroll
    for (int mi = 0; mi < 4; mi++)
        #pragma unroll
        for (int ni = 0; ni < 8; ni++)
            #pragma unroll
            for (int j = 0; j < 4; j++) acc[mi][ni][j] = 0.f;

    load_stage(0, 0);
    load_stage(1, 1);

    const int a_row_off = wr * 64 + (lane & 15);
    const int a_chunk_h = lane >> 4;
    const int b_row_off = wc * 64 + ((lane >> 4) << 3) + (lane & 7);
    const int b_chunk_h = (lane >> 3) & 1;

    for (int c = 0; c < nc; c++) {
        int s = c % 3;
        if (c + 1 < nc) asm volatile("cp.async.wait_group 1;" ::: "memory");
        else            asm volatile("cp.async.wait_group 0;" ::: "memory");
        __syncthreads();
        if (c + 2 < nc) load_stage(c + 2, (c + 2) % 3);

        uint32_t sa = base + s * 32768;
        uint32_t sb = sa + 16384;

        #pragma unroll
        for (int ks = 0; ks < 4; ks++) {
            uint32_t a[4][4];
            #pragma unroll
            for (int mi = 0; mi < 4; mi++) {
                uint32_t off = (uint32_t)((a_row_off + mi * 16) * 128
                                          + (ks * 2 + a_chunk_h) * 16);
                ldmatrix_x4(a[mi], sa + sw128(off));
            }
            uint32_t b[4][4];
            #pragma unroll
            for (int g = 0; g < 4; g++) {
                uint32_t off = (uint32_t)((b_row_off + g * 16) * 128
                                          + (ks * 2 + b_chunk_h) * 16);
                ldmatrix_x4(b[g], sb + sw128(off));
            }
            #pragma unroll
            for (int mi = 0; mi < 4; mi++)
                #pragma unroll
                for (int g = 0; g < 4; g++) {
                    mma16816(acc[mi][2 * g],     a[mi], b[g][0], b[g][1]);
                    mma16816(acc[mi][2 * g + 1], a[mi], b[g][2], b[g][3]);
                }
        }
    }

    // ---- fused epilogue: RoPE (q,k) or plain (v) + hi/lo split ----
    const int colbase = bcol + wc * 64;        // multiple of 64, one head section
    const int sect = colbase >> 10;            // 0=q, 1=k, 2=v
    const int h = (colbase >> 6) & 15;
    const float qscale = 0.125f * 1.44269504088896f;

    #pragma unroll
    for (int mi = 0; mi < 4; mi++) {
        #pragma unroll
        for (int jr = 0; jr < 2; jr++) {
            int row = brow + wr * 64 + mi * 16 + (lane >> 2) + jr * 8;
            int bb_ = row >> 11;
            int s = row & (SEQ - 1);
            size_t obase = (((size_t)(bb_ * HEADS + h)) * SEQ + s) * DHEAD;
            if (sect < 2) {
                __nv_bfloat16* H = (sect == 0) ? g_qh : g_kh;
                __nv_bfloat16* L = (sect == 0) ? g_ql : g_kl;
                #pragma unroll
                for (int ni = 0; ni < 4; ni++) {
                    int dlo = ni * 8 + (lane & 3) * 2;
                    float2 cs0 = g_cs[s * 32 + dlo];
                    float2 cs1 = g_cs[s * 32 + dlo + 1];
                    float xl0 = acc[mi][ni][jr * 2 + 0];
                    float xl1 = acc[mi][ni][jr * 2 + 1];
                    float xh0 = acc[mi][ni + 4][jr * 2 + 0];
                    float xh1 = acc[mi][ni + 4][jr * 2 + 1];
                    float rl0 = xl0 * cs0.x - xh0 * cs0.y;
                    float rl1 = xl1 * cs1.x - xh1 * cs1.y;
                    float rh0 = xh0 * cs0.x + xl0 * cs0.y;
                    float rh1 = xh1 * cs1.x + xl1 * cs1.y;
                    if (sect == 0) {
                        rl0 *= qscale; rl1 *= qscale;
                        rh0 *= qscale; rh1 *= qscale;
                    }
                    __nv_bfloat162 hp, lp;
                    split2(rl0, rl1, hp, lp);
                    *(__nv_bfloat162*)(H + obase + dlo) = hp;
                    *(__nv_bfloat162*)(L + obase + dlo) = lp;
                    split2(rh0, rh1, hp, lp);
                    *(__nv_bfloat162*)(H + obase + dlo + 32) = hp;
                    *(__nv_bfloat162*)(L + obase + dlo + 32) = lp;
                }
            } else {
                #pragma unroll
                for (int ni = 0; ni < 8; ni++) {
                    int d = ni * 8 + (lane & 3) * 2;
                    __nv_bfloat162 hp, lp;
                    split2(acc[mi][ni][jr * 2 + 0], acc[mi][ni][jr * 2 + 1], hp, lp);
                    *(__nv_bfloat162*)(g_vh + obase + d) = hp;
                    *(__nv_bfloat162*)(g_vl + obase + d) = lp;
                }
            }
        }
    }
}

// ==================== flash attention via HMMA (hi/lo split) =================
// Block: one (bh, 128-q tile). 4 warps x 32 q rows. KV tiles of 64, double buffered.
// S-phase shares A (qh,ql) and B (kh,kl) fragments across all 3 hi/lo passes.
__global__ __launch_bounds__(128) void flash_mma(__nv_bfloat16* __restrict__ abuf) {
    extern __shared__ __align__(1024) char smem[];
    const uint32_t base = smem_u32(smem);
    const int tid  = threadIdx.x;
    const int wid  = tid >> 5;
    const int lane = tid & 31;
    const int bh = blockIdx.y;
    const int qt = blockIdx.x;
    const int b = bh >> 4, h = bh & 15;

    const __nv_bfloat16* qhp = g_qh + ((size_t)bh * SEQ + qt * 128) * DHEAD;
    const __nv_bfloat16* qlp = g_ql + ((size_t)bh * SEQ + qt * 128) * DHEAD;

    #pragma unroll
    for (int t = 0; t < 8; t++) {
        int l = tid + t * 128;
        int r = l >> 3, c = l & 7;
        uint32_t sw = sw128((uint32_t)(r * 128 + c * 16));
        cp_async16(base + sw,         qhp + (size_t)r * DHEAD + c * 8);
        cp_async16(base + 16384 + sw, qlp + (size_t)r * DHEAD + c * 8);
    }
    cp_commit();

    auto load_kv = [&](int it, int s) {
        uint32_t st = base + 32768 + s * 32768;
        const __nv_bfloat16* khp = g_kh + ((size_t)bh * SEQ + it * 64) * DHEAD;
        const __nv_bfloat16* klp = g_kl + ((size_t)bh * SEQ + it * 64) * DHEAD;
        const __nv_bfloat16* vhp = g_vh + ((size_t)bh * SEQ + it * 64) * DHEAD;
        const __nv_bfloat16* vlp = g_vl + ((size_t)bh * SEQ + it * 64) * DHEAD;
        #pragma unroll
        for (int t = 0; t < 4; t++) {
            int l = tid + t * 128;
            int r = l >> 3, c = l & 7;
            uint32_t sw = sw128((uint32_t)(r * 128 + c * 16));
            cp_async16(st + sw,          khp + (size_t)r * DHEAD + c * 8);
            cp_async16(st + 8192 + sw,   klp + (size_t)r * DHEAD + c * 8);
            cp_async16(st + 16384 + sw,  vhp + (size_t)r * DHEAD + c * 8);
            cp_async16(st + 24576 + sw,  vlp + (size_t)r * DHEAD + c * 8);
        }
        cp_commit();
    };

    load_kv(0, 0);
    load_kv(1, 1);

    const int a_row  = wid * 32 + (lane & 15);
    const int a_chh  = lane >> 4;
    const int b_row  = ((lane >> 4) << 3) + (lane & 7);
    const int b_chh  = (lane >> 3) & 1;
    // trans-V address components: k(s)-row and n(d)-byte
    const int v_row  = ((lane >> 3) & 1) * 8 + (lane & 7);
    const int v_byte = (lane >> 4) * 16;

    float Oacc[2][8][4];
    #pragma unroll
    for (int mi = 0; mi < 2; mi++)
        #pragma unroll
        for (int n = 0; n < 8; n++)
            #pragma unroll
            for (int j = 0; j < 4; j++) Oacc[mi][n][j] = 0.f;
    float mrow[2][2] = {{-INFINITY, -INFINITY}, {-INFINITY, -INFINITY}};
    float lrow[2][2] = {{0.f, 0.f}, {0.f, 0.f}};

    const int nIter = SEQ / 64;
    for (int it = 0; it < nIter; it++) {
        int s = it & 1;
        if (it + 1 < nIter) asm volatile("cp.async.wait_group 1;" ::: "memory");
        else                asm volatile("cp.async.wait_group 0;" ::: "memory");
        __syncthreads();

        uint32_t st  = base + 32768 + s * 32768;
        uint32_t sqh = base, sql = base + 16384;
        uint32_t skh = st, skl = st + 8192, svh = st + 16384, svl = st + 24576;

        float sacc[2][8][4];
        #pragma unroll
        for (int mi = 0; mi < 2; mi++)
            #pragma unroll
            for (int n = 0; n < 8; n++)
                #pragma unroll
                for (int j = 0; j < 4; j++) sacc[mi][n][j] = 0.f;

        // ---- S = Qh Kh^T + Ql Kh^T + Qh Kl^T  (shared fragment loads) ----
        #pragma unroll
        for (int ks = 0; ks < 4; ks++) {
            uint32_t ah[2][4], al[2][4];
            #pragma unroll
            for (int mi = 0; mi < 2; mi++) {
                uint32_t aoff = (uint32_t)((a_row + mi * 16) * 128 + (ks * 2 + a_chh) * 16);
                ldmatrix_x4(ah[mi], sqh + sw128(aoff));
                ldmatrix_x4(al[mi], sql + sw128(aoff));
            }
            #pragma unroll
            for (int g = 0; g < 4; g++) {
                uint32_t boff = (uint32_t)((g * 16 + b_row) * 128 + (ks * 2 + b_chh) * 16);
                uint32_t bbh[4], bbl[4];
                ldmatrix_x4(bbh, skh + sw128(boff));
                ldmatrix_x4(bbl, skl + sw128(boff));
                #pragma unroll
                for (int mi = 0; mi < 2; mi++) {
                    mma16816(sacc[mi][2 * g],     ah[mi], bbh[0], bbh[1]);
                    mma16816(sacc[mi][2 * g + 1], ah[mi], bbh[2], bbh[3]);
                    mma16816(sacc[mi][2 * g],     al[mi], bbh[0], bbh[1]);
                    mma16816(sacc[mi][2 * g + 1], al[mi], bbh[2], bbh[3]);
                    mma16816(sacc[mi][2 * g],     ah[mi], bbl[0], bbl[1]);
                    mma16816(sacc[mi][2 * g + 1], ah[mi], bbl[2], bbl[3]);
                }
            }
        }

        // ---- register online softmax (exp2 domain) ----
        uint32_t pah[2][4][4], pal[2][4][4];
        #pragma unroll
        for (int mi = 0; mi < 2; mi++) {
            float mx0 = mrow[mi][0], mx1 = mrow[mi][1];
            #pragma unroll
            for (int n = 0; n < 8; n++) {
                mx0 = fmaxf(mx0, fmaxf(sacc[mi][n][0], sacc[mi][n][1]));
                mx1 = fmaxf(mx1, fmaxf(sacc[mi][n][2], sacc[mi][n][3]));
            }
            mx0 = fmaxf(mx0, __shfl_xor_sync(0xffffffff, mx0, 1));
            mx0 = fmaxf(mx0, __shfl_xor_sync(0xffffffff, mx0, 2));
            mx1 = fmaxf(mx1, __shfl_xor_sync(0xffffffff, mx1, 1));
            mx1 = fmaxf(mx1, __shfl_xor_sync(0xffffffff, mx1, 2));
            float corr0 = exp2f(mrow[mi][0] - mx0);
            float corr1 = exp2f(mrow[mi][1] - mx1);
            mrow[mi][0] = mx0; mrow[mi][1] = mx1;

            float sum0 = 0.f, sum1 = 0.f;
            #pragma unroll
            for (int n = 0; n < 8; n++) {
                float p0 = exp2f(sacc[mi][n][0] - mx0);
                float p1 = exp2f(sacc[mi][n][1] - mx0);
                float p2 = exp2f(sacc[mi][n][2] - mx1);
                float p3 = exp2f(sacc[mi][n][3] - mx1);
                sum0 += p0 + p1; sum1 += p2 + p3;
                __nv_bfloat16 h0 = __float2bfloat16(p0), h1 = __float2bfloat16(p1);
                __nv_bfloat16 h2 = __float2bfloat16(p2), h3 = __float2bfloat16(p3);
                int ks = n >> 1, hf = (n & 1) * 2;
                __nv_bfloat162 ph01 = {h0, h1}, ph23 = {h2, h3};
                pah[mi][ks][hf]     = *(uint32_t*)&ph01;
                pah[mi][ks][hf + 1] = *(uint32_t*)&ph23;
                __nv_bfloat162 pl01 = {__float2bfloat16(p0 - __bfloat162float(h0)),
                                       __float2bfloat16(p1 - __bfloat162float(h1))};
                __nv_bfloat162 pl23 = {__float2bfloat16(p2 - __bfloat162float(h2)),
                                       __float2bfloat16(p3 - __bfloat162float(h3))};
                pal[mi][ks][hf]     = *(uint32_t*)&pl01;
                pal[mi][ks][hf + 1] = *(uint32_t*)&pl23;
            }
            lrow[mi][0] = lrow[mi][0] * corr0 + sum0;
            lrow[mi][1] = lrow[mi][1] * corr1 + sum1;
            #pragma unroll
            for (int n = 0; n < 8; n++) {
                Oacc[mi][n][0] *= corr0; Oacc[mi][n][1] *= corr0;
                Oacc[mi][n][2] *= corr1; Oacc[mi][n][3] *= corr1;
            }
        }

        // ---- O += Ph Vh + Pl Vh + Ph Vl  (V via ldmatrix.trans from [s,d]) ----
        #pragma unroll
        for (int ks = 0; ks < 4; ks++) {
            #pragma unroll
            for (int g = 0; g < 4; g++) {
                uint32_t off = (uint32_t)((ks * 16 + v_row) * 128 + g * 32 + v_byte);
                uint32_t bh_[4], bl_[4];
                ldmatrix_x4_trans(bh_, svh + sw128(off));
                ldmatrix_x4_trans(bl_, svl + sw128(off));
                #pragma unroll
                for (int mi = 0; mi < 2; mi++) {
                    mma16816(Oacc[mi][2 * g],     pah[mi][ks], bh_[0], bh_[1]);
                    mma16816(Oacc[mi][2 * g + 1], pah[mi][ks], bh_[2], bh_[3]);
                    mma16816(Oacc[mi][2 * g],     pal[mi][ks], bh_[0], bh_[1]);
                    mma16816(Oacc[mi][2 * g + 1], pal[mi][ks], bh_[2], bh_[3]);
                    mma16816(Oacc[mi][2 * g],     pah[mi][ks], bl_[0], bl_[1]);
                    mma16816(Oacc[mi][2 * g + 1], pah[mi][ks], bl_[2], bl_[3]);
                }
            }
        }

        __syncthreads();
        if (it + 2 < nIter) load_kv(it + 2, s);
    }

    // ---- epilogue: normalize + hi/lo/hi split write into abuf [m, 3072] ----
    #pragma unroll
    for (int mi = 0; mi < 2; mi++) {
        float l0 = lrow[mi][0], l1 = lrow[mi][1];
        l0 += __shfl_xor_sync(0xffffffff, l0, 1);
        l0 += __shfl_xor_sync(0xffffffff, l0, 2);
        l1 += __shfl_xor_sync(0xffffffff, l1, 1);
        l1 += __shfl_xor_sync(0xffffffff, l1, 2);
        float inv0 = 1.f / l0, inv1 = 1.f / l1;
        int row0 = qt * 128 + wid * 32 + mi * 16 + (lane >> 2);
        #pragma unroll
        for (int n = 0; n < 8; n++) {
            int col = h * 64 + n * 8 + (lane & 3) * 2;
            __nv_bfloat16* p0 = abuf + (size_t)(b * SEQ + row0) * KSPLIT + col;
            __nv_bfloat16* p1 = abuf + (size_t)(b * SEQ + row0 + 8) * KSPLIT + col;
            __nv_bfloat162 hp, lp;
            split2(Oacc[mi][n][0] * inv0, Oacc[mi][n][1] * inv0, hp, lp);
            *(__nv_bfloat162*)(p0)        = hp;
            *(__nv_bfloat162*)(p0 + 1024) = lp;
            *(__nv_bfloat162*)(p0 + 2048) = hp;
            split2(Oacc[mi][n][2] * inv1, Oacc[mi][n][3] * inv1, hp, lp);
            *(__nv_bfloat162*)(p1)        = hp;
            *(__nv_bfloat162*)(p1 + 1024) = lp;
            *(__nv_bfloat162*)(p1 + 2048) = hp;
        }
    }
}

// -------------------- launch --------------------
extern "C" void kernel_launch(void* const* d_in, const int* in_sizes, int n_in,
                              void* d_out, int out_size) {
    const float* x     = (const float*)d_in[0];   // [2,2048,1024]
    const float* w_qkv = (const float*)d_in[1];   // [1024,3072]
    const float* w_out = (const float*)d_in[2];   // [1024,1024]
    float* out = (float*)d_out;                   // [2,2048,1024]

    __nv_bfloat16 *abuf, *btq, *bto;
    cudaGetSymbolAddress((void**)&abuf, g_abuf);
    cudaGetSymbolAddress((void**)&btq,  g_bt_qkv);
    cudaGetSymbolAddress((void**)&bto,  g_bt_out);

    const int kGemmSmem = 3 * 32768;   // 96 KB (3-stage)
    cudaFuncSetAttribute(bf16gemm_mma, cudaFuncAttributeMaxDynamicSharedMemorySize, kGemmSmem);
    cudaFuncSetAttribute(qkvgemm_rope, cudaFuncAttributeMaxDynamicSharedMemorySize, kGemmSmem);
    const int kFlashSmem = 32768 + 2 * 32768;   // 96 KB
    cudaFuncSetAttribute(flash_mma, cudaFuncAttributeMaxDynamicSharedMemorySize, kFlashSmem);

    // 0) cos/sin table + weight conversions
    init_cs<<<(SEQ * 32) / 256, 256>>>();
    split_bt<<<dim3(DMODEL / 32, QKV_N / 32), 256>>>(w_qkv, btq, DMODEL, QKV_N);
    split_bt<<<dim3(INNER / 32, DMODEL / 32), 256>>>(w_out, bto, INNER, DMODEL);

    // 1) split x, then QKV GEMM with fused RoPE + split epilogue
    split_rows<<<(BS * DMODEL / 4) / 256, 256>>>(x, abuf);
    qkvgemm_rope<<<dim3(QKV_N / 128, BS / 128), 128, kGemmSmem>>>(abuf, btq);

    // 2) flash attention (writes split ctx directly into abuf)
    flash_mma<<<dim3(SEQ / 128, BH), 128, kFlashSmem>>>(abuf);

    // 3) out = ctx @ w_out
    bf16gemm_mma<<<dim3(DMODEL / 128, BS / 128), 128, kGemmSmem>>>(abuf, bto, out, BS, DMODEL, KSPLIT);
}

// round 13
// speedup vs baseline: 1.0296x; 1.0296x over previous
#include <cuda_runtime.h>
#include <cuda_bf16.h>
#include <math.h>
#include <stdint.h>

// Problem constants
#define BATCH   2
#define SEQ     2048
#define DMODEL  1024
#define HEADS   16
#define DHEAD   64
#define INNER   (HEADS * DHEAD)          // 1024
#define BS      (BATCH * SEQ)            // 4096
#define QKV_N   (3 * INNER)              // 3072
#define KSPLIT  (3 * DMODEL)             // 3072 (hi | lo | hi split along K)
#define BH      (BATCH * HEADS)          // 32

// -------------------- scratch (static device allocations) --------------------
__device__ __nv_bfloat16 g_abuf[BS * KSPLIT];             // split A (x, then ctx)
__device__ __nv_bfloat16 g_bt_qkv[QKV_N * KSPLIT];        // split w_qkv^T
__device__ __nv_bfloat16 g_bt_out[DMODEL * KSPLIT];       // split w_out^T
// attention operands, bf16 hi/lo, all [bh, s, d]
__device__ __nv_bfloat16 g_qh[BH * SEQ * DHEAD];          // scaled+roped q hi
__device__ __nv_bfloat16 g_ql[BH * SEQ * DHEAD];
__device__ __nv_bfloat16 g_kh[BH * SEQ * DHEAD];          // roped k hi
__device__ __nv_bfloat16 g_kl[BH * SEQ * DHEAD];
__device__ __nv_bfloat16 g_vh[BH * SEQ * DHEAD];
__device__ __nv_bfloat16 g_vl[BH * SEQ * DHEAD];
__device__ float2 g_cs[SEQ * 32];                         // (cos, sin) table

// ==================== PTX helpers (sm_80-era, safe at compute_100) ===========
__device__ __forceinline__ uint32_t smem_u32(const void* p) {
    return (uint32_t)__cvta_generic_to_shared(p);
}
__device__ __forceinline__ void cp_async16(uint32_t dst, const void* src) {
    asm volatile("cp.async.cg.shared.global [%0], [%1], 16;\n" :: "r"(dst), "l"(src));
}
__device__ __forceinline__ void cp_commit() {
    asm volatile("cp.async.commit_group;\n" ::: "memory");
}
__device__ __forceinline__ void ldmatrix_x4(uint32_t* r, uint32_t addr) {
    asm volatile("ldmatrix.sync.aligned.m8n8.x4.shared.b16 {%0,%1,%2,%3}, [%4];"
                 : "=r"(r[0]), "=r"(r[1]), "=r"(r[2]), "=r"(r[3]) : "r"(addr));
}
__device__ __forceinline__ void ldmatrix_x4_trans(uint32_t* r, uint32_t addr) {
    asm volatile("ldmatrix.sync.aligned.m8n8.x4.trans.shared.b16 {%0,%1,%2,%3}, [%4];"
                 : "=r"(r[0]), "=r"(r[1]), "=r"(r[2]), "=r"(r[3]) : "r"(addr));
}
__device__ __forceinline__ void mma16816(float* c, const uint32_t* a,
                                         uint32_t b0, uint32_t b1) {
    asm volatile(
        "mma.sync.aligned.m16n8k16.row.col.f32.bf16.bf16.f32 "
        "{%0,%1,%2,%3}, {%4,%5,%6,%7}, {%8,%9}, {%0,%1,%2,%3};"
        : "+f"(c[0]), "+f"(c[1]), "+f"(c[2]), "+f"(c[3])
        : "r"(a[0]), "r"(a[1]), "r"(a[2]), "r"(a[3]), "r"(b0), "r"(b1));
}
__device__ __forceinline__ uint32_t sw128(uint32_t off) {
    return off ^ ((off >> 3) & 0x70);
}
// packed f32x2 -> bf16x2 (single F2FP.PACK, round-to-nearest)
__device__ __forceinline__ uint32_t pack_bf16x2(float v0, float v1) {
    __nv_bfloat162 p = __float22bfloat162_rn(make_float2(v0, v1));
    return *(uint32_t*)&p;
}
// hi/lo split a pair of fp32 into two bf16x2 (packed converts)
__device__ __forceinline__ void split2(float v0, float v1,
                                       __nv_bfloat162& hp, __nv_bfloat162& lp) {
    hp = __float22bfloat162_rn(make_float2(v0, v1));
    lp = __float22bfloat162_rn(make_float2(v0 - __bfloat162float(hp.x),
                                           v1 - __bfloat162float(hp.y)));
}

// ==================== cos/sin table ====================
__global__ __launch_bounds__(256) void init_cs() {
    int t = blockIdx.x * 256 + threadIdx.x;    // 0 .. SEQ*32-1
    int s = t >> 5, i = t & 31;
    float inv_freq = powf(10000.f, -(float)i / 32.f);
    float ang = (float)s * inv_freq;
    float sn, cn;
    __sincosf(ang, &sn, &cn);
    g_cs[t] = make_float2(cn, sn);
}

// ==================== conversion kernels (hi/lo bf16 split) ====================
// in [M,1024] fp32 row-major -> out [M,3072] bf16:  [hi | lo | hi]
__global__ __launch_bounds__(256) void split_rows(const float* __restrict__ in,
                                                  __nv_bfloat16* __restrict__ out) {
    int idx = blockIdx.x * 256 + threadIdx.x;
    int m  = idx >> 8;
    int kq = idx & 255;
    float4 v = ((const float4*)in)[(size_t)m * 256 + kq];
    __nv_bfloat162 hA, hB, lA, lB;
    split2(v.x, v.y, hA, lA);
    split2(v.z, v.w, hB, lB);
    __nv_bfloat162* o = (__nv_bfloat162*)(out + (size_t)m * KSPLIT + kq * 4);
    o[0] = hA; o[1] = hB;
    o[512] = lA; o[513] = lB;
    o[1024] = hA; o[1025] = hB;
}

// W [K,N] fp32 -> BT [N,3K] bf16 with [hi | hi | lo] along k'
__global__ __launch_bounds__(256) void split_bt(const float* __restrict__ W,
                                                __nv_bfloat16* __restrict__ BT,
                                                int K, int N) {
    __shared__ float tile[32][33];
    int k0 = blockIdx.x * 32, n0 = blockIdx.y * 32;
    for (int i = threadIdx.x; i < 1024; i += 256) {
        int r = i >> 5, c = i & 31;
        tile[r][c] = W[(size_t)(k0 + r) * N + n0 + c];
    }
    __syncthreads();
    for (int i = threadIdx.x; i < 1024; i += 256) {
        int rn = i >> 5, kc = i & 31;
        float v = tile[kc][rn];
        __nv_bfloat16 hi = __float2bfloat16(v);
        __nv_bfloat16 lo = __float2bfloat16(v - __bfloat162float(hi));
        __nv_bfloat16* row = BT + (size_t)(n0 + rn) * (3 * K) + k0 + kc;
        row[0]     = hi;
        row[K]     = hi;
        row[2 * K] = lo;
    }
}

// ==================== shared GEMM mainloop (2-stage, R11 config) ============
// CTA tile 128x128, BK=64, 128 threads = 2x2 warps of 64x64.

// ---- generic GEMM (used for out-projection): C fp32 [M,N] ----
__global__ __launch_bounds__(128) void bf16gemm_mma(const __nv_bfloat16* __restrict__ A,
                                                    const __nv_bfloat16* __restrict__ BT,
                                                    float* __restrict__ C,
                                                    int M, int N, int Kp) {
    extern __shared__ __align__(1024) char smem[];
    const uint32_t base = smem_u32(smem);
    const int tid  = threadIdx.x;
    const int wid  = tid >> 5;
    const int lane = tid & 31;
    const int wr   = wid >> 1;
    const int wc   = wid & 1;

    const int brow = blockIdx.y * 128;
    const int bcol = blockIdx.x * 128;
    const int nc   = Kp / 64;

    const __nv_bfloat16* Abase = A + (size_t)brow * Kp;
    const __nv_bfloat16* Bbase = BT + (size_t)bcol * Kp;

    auto load_stage = [&](int chunk, int s) {
        uint32_t sa = base + s * 32768;
        uint32_t sb = sa + 16384;
        const __nv_bfloat16* ac = Abase + chunk * 64;
        const __nv_bfloat16* bc = Bbase + chunk * 64;
        #pragma unroll
        for (int i = 0; i < 8; i++) {
            int l = tid + i * 128;
            int r = l >> 3;
            int c = l & 7;
            uint32_t sw = sw128((uint32_t)(r * 128 + c * 16));
            cp_async16(sa + sw, ac + (size_t)r * Kp + c * 8);
            cp_async16(sb + sw, bc + (size_t)r * Kp + c * 8);
        }
        cp_commit();
    };

    float acc[4][8][4];
    #pragma unroll
    for (int mi = 0; mi < 4; mi++)
        #pragma unroll
        for (int ni = 0; ni < 8; ni++)
            #pragma unroll
            for (int j = 0; j < 4; j++) acc[mi][ni][j] = 0.f;

    load_stage(0, 0);
    load_stage(1, 1);

    const int a_row_off = wr * 64 + (lane & 15);
    const int a_chunk_h = lane >> 4;
    const int b_row_off = wc * 64 + ((lane >> 4) << 3) + (lane & 7);
    const int b_chunk_h = (lane >> 3) & 1;

    for (int c = 0; c < nc; c++) {
        int s = c & 1;
        if (c + 1 < nc) asm volatile("cp.async.wait_group 1;" ::: "memory");
        else            asm volatile("cp.async.wait_group 0;" ::: "memory");
        __syncthreads();

        uint32_t sa = base + s * 32768;
        uint32_t sb = sa + 16384;

        #pragma unroll
        for (int ks = 0; ks < 4; ks++) {
            uint32_t a[4][4];
            #pragma unroll
            for (int mi = 0; mi < 4; mi++) {
                uint32_t off = (uint32_t)((a_row_off + mi * 16) * 128
                                          + (ks * 2 + a_chunk_h) * 16);
                ldmatrix_x4(a[mi], sa + sw128(off));
            }
            uint32_t b[4][4];
            #pragma unroll
            for (int g = 0; g < 4; g++) {
                uint32_t off = (uint32_t)((b_row_off + g * 16) * 128
                                          + (ks * 2 + b_chunk_h) * 16);
                ldmatrix_x4(b[g], sb + sw128(off));
            }
            #pragma unroll
            for (int mi = 0; mi < 4; mi++)
                #pragma unroll
                for (int g = 0; g < 4; g++) {
                    mma16816(acc[mi][2 * g],     a[mi], b[g][0], b[g][1]);
                    mma16816(acc[mi][2 * g + 1], a[mi], b[g][2], b[g][3]);
                }
        }
        __syncthreads();
        if (c + 2 < nc) load_stage(c + 2, s);
    }

    #pragma unroll
    for (int mi = 0; mi < 4; mi++) {
        int row0 = brow + wr * 64 + mi * 16 + (lane >> 2);
        #pragma unroll
        for (int ni = 0; ni < 8; ni++) {
            int col = bcol + wc * 64 + ni * 8 + (lane & 3) * 2;
            float2 v0 = {acc[mi][ni][0], acc[mi][ni][1]};
            float2 v1 = {acc[mi][ni][2], acc[mi][ni][3]};
            *(float2*)(C + (size_t)row0 * N + col) = v0;
            *(float2*)(C + (size_t)(row0 + 8) * N + col) = v1;
        }
    }
}

// ---- QKV GEMM with fused RoPE + hi/lo split epilogue ----
__global__ __launch_bounds__(128) void qkvgemm_rope(const __nv_bfloat16* __restrict__ A,
                                                    const __nv_bfloat16* __restrict__ BT) {
    extern __shared__ __align__(1024) char smem[];
    const uint32_t base = smem_u32(smem);
    const int tid  = threadIdx.x;
    const int wid  = tid >> 5;
    const int lane = tid & 31;
    const int wr   = wid >> 1;
    const int wc   = wid & 1;

    const int brow = blockIdx.y * 128;
    const int bcol = blockIdx.x * 128;
    const int Kp   = KSPLIT;
    const int nc   = Kp / 64;

    const __nv_bfloat16* Abase = A + (size_t)brow * Kp;
    const __nv_bfloat16* Bbase = BT + (size_t)bcol * Kp;

    auto load_stage = [&](int chunk, int s) {
        uint32_t sa = base + s * 32768;
        uint32_t sb = sa + 16384;
        const __nv_bfloat16* ac = Abase + chunk * 64;
        const __nv_bfloat16* bc = Bbase + chunk * 64;
        #pragma unroll
        for (int i = 0; i < 8; i++) {
            int l = tid + i * 128;
            int r = l >> 3;
            int c = l & 7;
            uint32_t sw = sw128((uint32_t)(r * 128 + c * 16));
            cp_async16(sa + sw, ac + (size_t)r * Kp + c * 8);
            cp_async16(sb + sw, bc + (size_t)r * Kp + c * 8);
        }
        cp_commit();
    };

    float acc[4][8][4];
    #pragma unroll
    for (int mi = 0; mi < 4; mi++)
        #pragma unroll
        for (int ni = 0; ni < 8; ni++)
            #pragma unroll
            for (int j = 0; j < 4; j++) acc[mi][ni][j] = 0.f;

    load_stage(0, 0);
    load_stage(1, 1);

    const int a_row_off = wr * 64 + (lane & 15);
    const int a_chunk_h = lane >> 4;
    const int b_row_off = wc * 64 + ((lane >> 4) << 3) + (lane & 7);
    const int b_chunk_h = (lane >> 3) & 1;

    for (int c = 0; c < nc; c++) {
        int s = c & 1;
        if (c + 1 < nc) asm volatile("cp.async.wait_group 1;" ::: "memory");
        else            asm volatile("cp.async.wait_group 0;" ::: "memory");
        __syncthreads();

        uint32_t sa = base + s * 32768;
        uint32_t sb = sa + 16384;

        #pragma unroll
        for (int ks = 0; ks < 4; ks++) {
            uint32_t a[4][4];
            #pragma unroll
            for (int mi = 0; mi < 4; mi++) {
                uint32_t off = (uint32_t)((a_row_off + mi * 16) * 128
                                          + (ks * 2 + a_chunk_h) * 16);
                ldmatrix_x4(a[mi], sa + sw128(off));
            }
            uint32_t b[4][4];
            #pragma unroll
            for (int g = 0; g < 4; g++) {
                uint32_t off = (uint32_t)((b_row_off + g * 16) * 128
                                          + (ks * 2 + b_chunk_h) * 16);
                ldmatrix_x4(b[g], sb + sw128(off));
            }
            #pragma unroll
            for (int mi = 0; mi < 4; mi++)
                #pragma unroll
                for (int g = 0; g < 4; g++) {
                    mma16816(acc[mi][2 * g],     a[mi], b[g][0], b[g][1]);
                    mma16816(acc[mi][2 * g + 1], a[mi], b[g][2], b[g][3]);
                }
        }
        __syncthreads();
        if (c + 2 < nc) load_stage(c + 2, s);
    }

    // ---- fused epilogue: RoPE (q,k) or plain (v) + hi/lo split ----
    const int colbase = bcol + wc * 64;        // multiple of 64, one head section
    const int sect = colbase >> 10;            // 0=q, 1=k, 2=v
    const int h = (colbase >> 6) & 15;
    const float qscale = 0.125f * 1.44269504088896f;

    #pragma unroll
    for (int mi = 0; mi < 4; mi++) {
        #pragma unroll
        for (int jr = 0; jr < 2; jr++) {
            int row = brow + wr * 64 + mi * 16 + (lane >> 2) + jr * 8;
            int bb_ = row >> 11;
            int s = row & (SEQ - 1);
            size_t obase = (((size_t)(bb_ * HEADS + h)) * SEQ + s) * DHEAD;
            if (sect < 2) {
                __nv_bfloat16* H = (sect == 0) ? g_qh : g_kh;
                __nv_bfloat16* L = (sect == 0) ? g_ql : g_kl;
                #pragma unroll
                for (int ni = 0; ni < 4; ni++) {
                    int dlo = ni * 8 + (lane & 3) * 2;
                    float2 cs0 = g_cs[s * 32 + dlo];
                    float2 cs1 = g_cs[s * 32 + dlo + 1];
                    float xl0 = acc[mi][ni][jr * 2 + 0];
                    float xl1 = acc[mi][ni][jr * 2 + 1];
                    float xh0 = acc[mi][ni + 4][jr * 2 + 0];
                    float xh1 = acc[mi][ni + 4][jr * 2 + 1];
                    float rl0 = xl0 * cs0.x - xh0 * cs0.y;
                    float rl1 = xl1 * cs1.x - xh1 * cs1.y;
                    float rh0 = xh0 * cs0.x + xl0 * cs0.y;
                    float rh1 = xh1 * cs1.x + xl1 * cs1.y;
                    if (sect == 0) {
                        rl0 *= qscale; rl1 *= qscale;
                        rh0 *= qscale; rh1 *= qscale;
                    }
                    __nv_bfloat162 hp, lp;
                    split2(rl0, rl1, hp, lp);
                    *(__nv_bfloat162*)(H + obase + dlo) = hp;
                    *(__nv_bfloat162*)(L + obase + dlo) = lp;
                    split2(rh0, rh1, hp, lp);
                    *(__nv_bfloat162*)(H + obase + dlo + 32) = hp;
                    *(__nv_bfloat162*)(L + obase + dlo + 32) = lp;
                }
            } else {
                #pragma unroll
                for (int ni = 0; ni < 8; ni++) {
                    int d = ni * 8 + (lane & 3) * 2;
                    __nv_bfloat162 hp, lp;
                    split2(acc[mi][ni][jr * 2 + 0], acc[mi][ni][jr * 2 + 1], hp, lp);
                    *(__nv_bfloat162*)(g_vh + obase + d) = hp;
                    *(__nv_bfloat162*)(g_vl + obase + d) = lp;
                }
            }
        }
    }
}

// ==================== flash attention via HMMA (hi/lo split) =================
// Block: one (bh, 128-q tile). 4 warps x 32 q rows. KV tiles of 64, double buffered.
// S-phase shares A (qh,ql) and B (kh,kl) fragments across all 3 hi/lo passes.
__global__ __launch_bounds__(128) void flash_mma(__nv_bfloat16* __restrict__ abuf) {
    extern __shared__ __align__(1024) char smem[];
    const uint32_t base = smem_u32(smem);
    const int tid  = threadIdx.x;
    const int wid  = tid >> 5;
    const int lane = tid & 31;
    const int bh = blockIdx.y;
    const int qt = blockIdx.x;
    const int b = bh >> 4, h = bh & 15;

    const __nv_bfloat16* qhp = g_qh + ((size_t)bh * SEQ + qt * 128) * DHEAD;
    const __nv_bfloat16* qlp = g_ql + ((size_t)bh * SEQ + qt * 128) * DHEAD;

    #pragma unroll
    for (int t = 0; t < 8; t++) {
        int l = tid + t * 128;
        int r = l >> 3, c = l & 7;
        uint32_t sw = sw128((uint32_t)(r * 128 + c * 16));
        cp_async16(base + sw,         qhp + (size_t)r * DHEAD + c * 8);
        cp_async16(base + 16384 + sw, qlp + (size_t)r * DHEAD + c * 8);
    }
    cp_commit();

    auto load_kv = [&](int it, int s) {
        uint32_t st = base + 32768 + s * 32768;
        const __nv_bfloat16* khp = g_kh + ((size_t)bh * SEQ + it * 64) * DHEAD;
        const __nv_bfloat16* klp = g_kl + ((size_t)bh * SEQ + it * 64) * DHEAD;
        const __nv_bfloat16* vhp = g_vh + ((size_t)bh * SEQ + it * 64) * DHEAD;
        const __nv_bfloat16* vlp = g_vl + ((size_t)bh * SEQ + it * 64) * DHEAD;
        #pragma unroll
        for (int t = 0; t < 4; t++) {
            int l = tid + t * 128;
            int r = l >> 3, c = l & 7;
            uint32_t sw = sw128((uint32_t)(r * 128 + c * 16));
            cp_async16(st + sw,          khp + (size_t)r * DHEAD + c * 8);
            cp_async16(st + 8192 + sw,   klp + (size_t)r * DHEAD + c * 8);
            cp_async16(st + 16384 + sw,  vhp + (size_t)r * DHEAD + c * 8);
            cp_async16(st + 24576 + sw,  vlp + (size_t)r * DHEAD + c * 8);
        }
        cp_commit();
    };

    load_kv(0, 0);
    load_kv(1, 1);

    const int a_row  = wid * 32 + (lane & 15);
    const int a_chh  = lane >> 4;
    const int b_row  = ((lane >> 4) << 3) + (lane & 7);
    const int b_chh  = (lane >> 3) & 1;
    // trans-V address components: k(s)-row and n(d)-byte
    const int v_row  = ((lane >> 3) & 1) * 8 + (lane & 7);
    const int v_byte = (lane >> 4) * 16;

    float Oacc[2][8][4];
    #pragma unroll
    for (int mi = 0; mi < 2; mi++)
        #pragma unroll
        for (int n = 0; n < 8; n++)
            #pragma unroll
            for (int j = 0; j < 4; j++) Oacc[mi][n][j] = 0.f;
    float mrow[2][2] = {{-INFINITY, -INFINITY}, {-INFINITY, -INFINITY}};
    float lrow[2][2] = {{0.f, 0.f}, {0.f, 0.f}};

    const int nIter = SEQ / 64;
    for (int it = 0; it < nIter; it++) {
        int s = it & 1;
        if (it + 1 < nIter) asm volatile("cp.async.wait_group 1;" ::: "memory");
        else                asm volatile("cp.async.wait_group 0;" ::: "memory");
        __syncthreads();

        uint32_t st  = base + 32768 + s * 32768;
        uint32_t sqh = base, sql = base + 16384;
        uint32_t skh = st, skl = st + 8192, svh = st + 16384, svl = st + 24576;

        float sacc[2][8][4];
        #pragma unroll
        for (int mi = 0; mi < 2; mi++)
            #pragma unroll
            for (int n = 0; n < 8; n++)
                #pragma unroll
                for (int j = 0; j < 4; j++) sacc[mi][n][j] = 0.f;

        // ---- S = Qh Kh^T + Ql Kh^T + Qh Kl^T  (shared fragment loads) ----
        #pragma unroll
        for (int ks = 0; ks < 4; ks++) {
            uint32_t ah[2][4], al[2][4];
            #pragma unroll
            for (int mi = 0; mi < 2; mi++) {
                uint32_t aoff = (uint32_t)((a_row + mi * 16) * 128 + (ks * 2 + a_chh) * 16);
                ldmatrix_x4(ah[mi], sqh + sw128(aoff));
                ldmatrix_x4(al[mi], sql + sw128(aoff));
            }
            #pragma unroll
            for (int g = 0; g < 4; g++) {
                uint32_t boff = (uint32_t)((g * 16 + b_row) * 128 + (ks * 2 + b_chh) * 16);
                uint32_t bbh[4], bbl[4];
                ldmatrix_x4(bbh, skh + sw128(boff));
                ldmatrix_x4(bbl, skl + sw128(boff));
                #pragma unroll
                for (int mi = 0; mi < 2; mi++) {
                    mma16816(sacc[mi][2 * g],     ah[mi], bbh[0], bbh[1]);
                    mma16816(sacc[mi][2 * g + 1], ah[mi], bbh[2], bbh[3]);
                    mma16816(sacc[mi][2 * g],     al[mi], bbh[0], bbh[1]);
                    mma16816(sacc[mi][2 * g + 1], al[mi], bbh[2], bbh[3]);
                    mma16816(sacc[mi][2 * g],     ah[mi], bbl[0], bbl[1]);
                    mma16816(sacc[mi][2 * g + 1], ah[mi], bbl[2], bbl[3]);
                }
            }
        }

        // ---- register online softmax (exp2 domain, packed bf16 converts) ----
        uint32_t pah[2][4][4], pal[2][4][4];
        #pragma unroll
        for (int mi = 0; mi < 2; mi++) {
            float mx0 = mrow[mi][0], mx1 = mrow[mi][1];
            #pragma unroll
            for (int n = 0; n < 8; n++) {
                mx0 = fmaxf(mx0, fmaxf(sacc[mi][n][0], sacc[mi][n][1]));
                mx1 = fmaxf(mx1, fmaxf(sacc[mi][n][2], sacc[mi][n][3]));
            }
            mx0 = fmaxf(mx0, __shfl_xor_sync(0xffffffff, mx0, 1));
            mx0 = fmaxf(mx0, __shfl_xor_sync(0xffffffff, mx0, 2));
            mx1 = fmaxf(mx1, __shfl_xor_sync(0xffffffff, mx1, 1));
            mx1 = fmaxf(mx1, __shfl_xor_sync(0xffffffff, mx1, 2));
            float corr0 = exp2f(mrow[mi][0] - mx0);
            float corr1 = exp2f(mrow[mi][1] - mx1);
            mrow[mi][0] = mx0; mrow[mi][1] = mx1;

            float sum0 = 0.f, sum1 = 0.f;
            #pragma unroll
            for (int n = 0; n < 8; n++) {
                float p0 = exp2f(sacc[mi][n][0] - mx0);
                float p1 = exp2f(sacc[mi][n][1] - mx0);
                float p2 = exp2f(sacc[mi][n][2] - mx1);
                float p3 = exp2f(sacc[mi][n][3] - mx1);
                sum0 += p0 + p1; sum1 += p2 + p3;
                int ks = n >> 1, hf = (n & 1) * 2;
                __nv_bfloat162 h01, l01, h23, l23;
                split2(p0, p1, h01, l01);
                split2(p2, p3, h23, l23);
                pah[mi][ks][hf]     = *(uint32_t*)&h01;
                pah[mi][ks][hf + 1] = *(uint32_t*)&h23;
                pal[mi][ks][hf]     = *(uint32_t*)&l01;
                pal[mi][ks][hf + 1] = *(uint32_t*)&l23;
            }
            lrow[mi][0] = lrow[mi][0] * corr0 + sum0;
            lrow[mi][1] = lrow[mi][1] * corr1 + sum1;
            #pragma unroll
            for (int n = 0; n < 8; n++) {
                Oacc[mi][n][0] *= corr0; Oacc[mi][n][1] *= corr0;
                Oacc[mi][n][2] *= corr1; Oacc[mi][n][3] *= corr1;
            }
        }

        // ---- O += Ph Vh + Pl Vh + Ph Vl  (V via ldmatrix.trans from [s,d]) ----
        #pragma unroll
        for (int ks = 0; ks < 4; ks++) {
            #pragma unroll
            for (int g = 0; g < 4; g++) {
                uint32_t off = (uint32_t)((ks * 16 + v_row) * 128 + g * 32 + v_byte);
                uint32_t bh_[4], bl_[4];
                ldmatrix_x4_trans(bh_, svh + sw128(off));
                ldmatrix_x4_trans(bl_, svl + sw128(off));
                #pragma unroll
                for (int mi = 0; mi < 2; mi++) {
                    mma16816(Oacc[mi][2 * g],     pah[mi][ks], bh_[0], bh_[1]);
                    mma16816(Oacc[mi][2 * g + 1], pah[mi][ks], bh_[2], bh_[3]);
                    mma16816(Oacc[mi][2 * g],     pal[mi][ks], bh_[0], bh_[1]);
                    mma16816(Oacc[mi][2 * g + 1], pal[mi][ks], bh_[2], bh_[3]);
                    mma16816(Oacc[mi][2 * g],     pah[mi][ks], bl_[0], bl_[1]);
                    mma16816(Oacc[mi][2 * g + 1], pah[mi][ks], bl_[2], bl_[3]);
                }
            }
        }

        __syncthreads();
        if (it + 2 < nIter) load_kv(it + 2, s);
    }

    // ---- epilogue: normalize + hi/lo/hi split write into abuf [m, 3072] ----
    #pragma unroll
    for (int mi = 0; mi < 2; mi++) {
        float l0 = lrow[mi][0], l1 = lrow[mi][1];
        l0 += __shfl_xor_sync(0xffffffff, l0, 1);
        l0 += __shfl_xor_sync(0xffffffff, l0, 2);
        l1 += __shfl_xor_sync(0xffffffff, l1, 1);
        l1 += __shfl_xor_sync(0xffffffff, l1, 2);
        float inv0 = 1.f / l0, inv1 = 1.f / l1;
        int row0 = qt * 128 + wid * 32 + mi * 16 + (lane >> 2);
        #pragma unroll
        for (int n = 0; n < 8; n++) {
            int col = h * 64 + n * 8 + (lane & 3) * 2;
            __nv_bfloat16* p0 = abuf + (size_t)(b * SEQ + row0) * KSPLIT + col;
            __nv_bfloat16* p1 = abuf + (size_t)(b * SEQ + row0 + 8) * KSPLIT + col;
            __nv_bfloat162 hp, lp;
            split2(Oacc[mi][n][0] * inv0, Oacc[mi][n][1] * inv0, hp, lp);
            *(__nv_bfloat162*)(p0)        = hp;
            *(__nv_bfloat162*)(p0 + 1024) = lp;
            *(__nv_bfloat162*)(p0 + 2048) = hp;
            split2(Oacc[mi][n][2] * inv1, Oacc[mi][n][3] * inv1, hp, lp);
            *(__nv_bfloat162*)(p1)        = hp;
            *(__nv_bfloat162*)(p1 + 1024) = lp;
            *(__nv_bfloat162*)(p1 + 2048) = hp;
        }
    }
}

// -------------------- launch --------------------
extern "C" void kernel_launch(void* const* d_in, const int* in_sizes, int n_in,
                              void* d_out, int out_size) {
    const float* x     = (const float*)d_in[0];   // [2,2048,1024]
    const float* w_qkv = (const float*)d_in[1];   // [1024,3072]
    const float* w_out = (const float*)d_in[2];   // [1024,1024]
    float* out = (float*)d_out;                   // [2,2048,1024]

    __nv_bfloat16 *abuf, *btq, *bto;
    cudaGetSymbolAddress((void**)&abuf, g_abuf);
    cudaGetSymbolAddress((void**)&btq,  g_bt_qkv);
    cudaGetSymbolAddress((void**)&bto,  g_bt_out);

    const int kGemmSmem = 2 * 32768;   // 64 KB (2-stage, reverted)
    cudaFuncSetAttribute(bf16gemm_mma, cudaFuncAttributeMaxDynamicSharedMemorySize, kGemmSmem);
    cudaFuncSetAttribute(qkvgemm_rope, cudaFuncAttributeMaxDynamicSharedMemorySize, kGemmSmem);
    const int kFlashSmem = 32768 + 2 * 32768;   // 96 KB
    cudaFuncSetAttribute(flash_mma, cudaFuncAttributeMaxDynamicSharedMemorySize, kFlashSmem);

    // 0) cos/sin table + weight conversions
    init_cs<<<(SEQ * 32) / 256, 256>>>();
    split_bt<<<dim3(DMODEL / 32, QKV_N / 32), 256>>>(w_qkv, btq, DMODEL, QKV_N);
    split_bt<<<dim3(INNER / 32, DMODEL / 32), 256>>>(w_out, bto, INNER, DMODEL);

    // 1) split x, then QKV GEMM with fused RoPE + split epilogue
    split_rows<<<(BS * DMODEL / 4) / 256, 256>>>(x, abuf);
    qkvgemm_rope<<<dim3(QKV_N / 128, BS / 128), 128, kGemmSmem>>>(abuf, btq);

    // 2) flash attention (writes split ctx directly into abuf)
    flash_mma<<<dim3(SEQ / 128, BH), 128, kFlashSmem>>>(abuf);

    // 3) out = ctx @ w_out
    bf16gemm_mma<<<dim3(DMODEL / 128, BS / 128), 128, kGemmSmem>>>(abuf, bto, out, BS, DMODEL, KSPLIT);
}